// round 13
// baseline (speedup 1.0000x reference)
#include <cuda_runtime.h>
#include <math.h>
#include <stdint.h>

#define S_LEN 2048
#define BATCH 4
#define DMODEL 1024
#define HN 16
#define DKH 64
#define DFF 4096
#define NTOK (BATCH * S_LEN)   // 8192

// ---------------- scratch (static device globals; no runtime allocation) ----
__device__ float g_h  [NTOK * DMODEL];
__device__ float g_q  [NTOK * DMODEL];
__device__ float g_k  [NTOK * DMODEL];
__device__ float g_v  [NTOK * DMODEL];
__device__ float g_ctx[NTOK * DMODEL];
__device__ float g_x2 [NTOK * DMODEL];
__device__ float g_ffn[(size_t)NTOK * DFF];

// ---------------- helpers ----------------------------------------------------
__device__ __forceinline__ void cp16(void* s, const void* g) {
    unsigned sa = (unsigned)__cvta_generic_to_shared(s);
    asm volatile("cp.async.cg.shared.global [%0], [%1], 16;" :: "r"(sa), "l"(g));
}
#define CP_COMMIT() asm volatile("cp.async.commit_group;")
#define CP_WAIT0()  asm volatile("cp.async.wait_group 0;")
#define CP_WAIT1()  asm volatile("cp.async.wait_group 1;")

// raw fp32 bits into tf32 mma: HW truncates to 19 bits (no cvt needed)
#define MMA_TF32(d, a, b)                                                     \
    asm volatile(                                                             \
        "mma.sync.aligned.m16n8k8.row.col.f32.tf32.tf32.f32 "                 \
        "{%0,%1,%2,%3},{%4,%5,%6,%7},{%8,%9},{%0,%1,%2,%3};"                  \
        : "+f"((d)[0]), "+f"((d)[1]), "+f"((d)[2]), "+f"((d)[3])              \
        : "r"((a)[0]), "r"((a)[1]), "r"((a)[2]), "r"((a)[3]),                 \
          "r"((b)[0]), "r"((b)[1]))

// ---------------- LayerNorm (torch semantics) --------------------------------
__global__ void ln_kernel(const float* __restrict__ x, float* __restrict__ y,
                          const float* __restrict__ ga, const float* __restrict__ gb)
{
    int row = blockIdx.x;
    const float4* xr = (const float4*)(x + (size_t)row * DMODEL);
    float4* yr = (float4*)(y + (size_t)row * DMODEL);
    int t = threadIdx.x;
    float4 v = xr[t];
    float s  = v.x + v.y + v.z + v.w;
    float ss = v.x*v.x + v.y*v.y + v.z*v.z + v.w*v.w;
    #pragma unroll
    for (int o = 16; o > 0; o >>= 1) {
        s  += __shfl_xor_sync(0xffffffffu, s,  o);
        ss += __shfl_xor_sync(0xffffffffu, ss, o);
    }
    __shared__ float rs[8], rss[8];
    __shared__ float sh_mean, sh_inv, sh_beta;
    int w = t >> 5;
    if ((t & 31) == 0) { rs[w] = s; rss[w] = ss; }
    __syncthreads();
    if (t == 0) {
        float S = 0.f, SS = 0.f;
        #pragma unroll
        for (int i = 0; i < 8; i++) { S += rs[i]; SS += rss[i]; }
        float mean = S / (float)DMODEL;
        float var  = (SS - (float)DMODEL * mean * mean) / (float)(DMODEL - 1);
        var = fmaxf(var, 0.f);
        sh_mean = mean;
        sh_inv  = ga[0] / (sqrtf(var) + 1e-5f);
        sh_beta = gb[0];
    }
    __syncthreads();
    float mean = sh_mean, inv = sh_inv, beta = sh_beta;
    float4 o;
    o.x = (v.x - mean) * inv + beta;
    o.y = (v.y - mean) * inv + beta;
    o.z = (v.z - mean) * inv + beta;
    o.w = (v.w - mean) * inv + beta;
    yr[t] = o;
}

// ---------------- TF32 tensor-core GEMM, cp.async 3-stage --------------------
// C[M,N] = A[M,K] @ W[N,K]^T + bias (+resid)(relu)
// Block 128x128, BK=32, 3-stage cp.async, 256 thr = 8 warps (2x4),
// warp tile 64x32, 2 CTAs/SM. XOR swizzle on 16B chunks: chunk ^= row&7
// -> conflict-free cp.async stores and fragment LDS (bank = 4*(2ks^g)+tg).
#define GEMM_SMEM_BYTES (3 * 2 * 128 * 32 * 4)   // 98304

// float index of element (r,c) in a swizzled [128][32] tile
__device__ __forceinline__ int swz(int r, int c) {
    return r * 32 + ((((c >> 2) ^ (r & 7)) << 2) | (c & 3));
}

template<bool RELU, bool RESID>
__device__ __forceinline__ void gemm_body(
    const float* __restrict__ A, const float* __restrict__ W,
    const float* __restrict__ bias, const float* __restrict__ resid,
    float* __restrict__ C, int N, int K, int bm, int bn)
{
    extern __shared__ float sm[];
    float* As = sm;                      // [3][128*32]
    float* Bs = sm + 3 * 128 * 32;       // [3][128*32]

    const int tid  = threadIdx.x;
    const int lane = tid & 31;
    const int warp = tid >> 5;
    const int g    = lane >> 2;
    const int tg   = lane & 3;
    const int wm   = (warp >> 2) * 64;
    const int wn   = (warp & 3) * 32;

    // cp.async mapping: 2 threads per row, 4 x 16B chunks each
    const int lr = tid >> 1;             // 0..127
    const int c4 = (tid & 1) * 4;        // chunk base 0 or 4
    const float* Ag = A + (size_t)(bm + lr) * K + c4 * 4;
    const float* Wg = W + (size_t)(bn + lr) * K + c4 * 4;
    int soff[4];
    #pragma unroll
    for (int i = 0; i < 4; i++)
        soff[i] = lr * 32 + (((c4 + i) ^ (lr & 7)) << 2);

    float acc[4][4][4];
    #pragma unroll
    for (int mi = 0; mi < 4; mi++)
        #pragma unroll
        for (int ni = 0; ni < 4; ni++)
            #pragma unroll
            for (int c = 0; c < 4; c++) acc[mi][ni][c] = 0.f;

    const int nchunk = K / 32;

    // prologue: stage slabs 0 and 1
    #pragma unroll
    for (int p = 0; p < 2; p++) {
        float* Ad = As + p * 128 * 32;
        float* Bd = Bs + p * 128 * 32;
        #pragma unroll
        for (int i = 0; i < 4; i++) {
            cp16(Ad + soff[i], Ag + p * 32 + i * 4);
            cp16(Bd + soff[i], Wg + p * 32 + i * 4);
        }
        CP_COMMIT();
    }

    int buf = 0;
    for (int ch = 0; ch < nchunk; ch++) {
        if (ch + 1 < nchunk) CP_WAIT1(); else CP_WAIT0();
        __syncthreads();   // slab ch ready; all warps done with buf (ch+2)%3

        if (ch + 2 < nchunk) {
            const int nb = ((buf + 2 >= 3) ? buf - 1 : buf + 2) * 128 * 32;
            const int k0 = (ch + 2) * 32;
            #pragma unroll
            for (int i = 0; i < 4; i++) {
                cp16(As + nb + soff[i], Ag + k0 + i * 4);
                cp16(Bs + nb + soff[i], Wg + k0 + i * 4);
            }
            CP_COMMIT();
        }

        const float* Ab = As + buf * 128 * 32;
        const float* Bb = Bs + buf * 128 * 32;
        #pragma unroll
        for (int ks = 0; ks < 4; ks++) {
            unsigned a[4][4], b[4][2];
            const int c = ks * 8 + tg;
            #pragma unroll
            for (int mi = 0; mi < 4; mi++) {
                const int r = wm + mi * 16 + g;
                a[mi][0] = __float_as_uint(Ab[swz(r, c)]);
                a[mi][1] = __float_as_uint(Ab[swz(r + 8, c)]);
                a[mi][2] = __float_as_uint(Ab[swz(r, c + 4)]);
                a[mi][3] = __float_as_uint(Ab[swz(r + 8, c + 4)]);
            }
            #pragma unroll
            for (int ni = 0; ni < 4; ni++) {
                const int r = wn + ni * 8 + g;
                b[ni][0] = __float_as_uint(Bb[swz(r, c)]);
                b[ni][1] = __float_as_uint(Bb[swz(r, c + 4)]);
            }
            #pragma unroll
            for (int mi = 0; mi < 4; mi++)
                #pragma unroll
                for (int ni = 0; ni < 4; ni++)
                    MMA_TF32(acc[mi][ni], a[mi], b[ni]);
        }
        buf = (buf + 1 >= 3) ? 0 : buf + 1;
    }

    // epilogue
    #pragma unroll
    for (int mi = 0; mi < 4; mi++) {
        int row0 = bm + wm + mi * 16 + g;
        #pragma unroll
        for (int ni = 0; ni < 4; ni++) {
            int col = bn + wn + ni * 8 + tg * 2;
            float bia0 = bias[col], bia1 = bias[col + 1];
            float v0 = acc[mi][ni][0] + bia0;
            float v1 = acc[mi][ni][1] + bia1;
            float v2 = acc[mi][ni][2] + bia0;
            float v3 = acc[mi][ni][3] + bia1;
            if (RESID) {
                const float* r0 = resid + (size_t)row0 * N + col;
                const float* r8 = resid + (size_t)(row0 + 8) * N + col;
                v0 += r0[0]; v1 += r0[1];
                v2 += r8[0]; v3 += r8[1];
            }
            if (RELU) {
                v0 = fmaxf(v0, 0.f); v1 = fmaxf(v1, 0.f);
                v2 = fmaxf(v2, 0.f); v3 = fmaxf(v3, 0.f);
            }
            *(float2*)(C + (size_t)row0 * N + col)       = make_float2(v0, v1);
            *(float2*)(C + (size_t)(row0 + 8) * N + col) = make_float2(v2, v3);
        }
    }
}

template<bool RELU, bool RESID>
__global__ void __launch_bounds__(256, 2) mma_gemm(
    const float* __restrict__ A, const float* __restrict__ W,
    const float* __restrict__ bias, const float* __restrict__ resid,
    float* __restrict__ C, int N, int K)
{
    gemm_body<RELU, RESID>(A, W, bias, resid, C, N, K,
                           blockIdx.y * 128, blockIdx.x * 128);
}

// merged QKV: blockIdx.z selects weight/bias/output
__global__ void __launch_bounds__(256, 2) mma_gemm_qkv(
    const float* __restrict__ A,
    const float* __restrict__ wq, const float* __restrict__ wk, const float* __restrict__ wv,
    const float* __restrict__ bq, const float* __restrict__ bk, const float* __restrict__ bv,
    float* __restrict__ oq, float* __restrict__ ok, float* __restrict__ ov)
{
    const int z = blockIdx.z;
    const float* W = (z == 0) ? wq : (z == 1) ? wk : wv;
    const float* B = (z == 0) ? bq : (z == 1) ? bk : bv;
    float*       C = (z == 0) ? oq : (z == 1) ? ok : ov;
    gemm_body<false, false>(A, W, B, nullptr, C, DMODEL, DMODEL,
                            blockIdx.y * 128, blockIdx.x * 128);
}

// ---------------- Flash attention on tf32 mma.sync ---------------------------
// Same structure as R8, but no tf32 cvts anywhere (HW truncation in mma).
#define FLASH_SMEM_BYTES ((64 * 68 * 3 + 64 * 72) * 4)

__global__ void __launch_bounds__(128) flash_mma(
    const float* __restrict__ Q, const float* __restrict__ Kg,
    const float* __restrict__ Vg, float* __restrict__ O)
{
    extern __shared__ float fsm[];
    float* sq = fsm;                 // [64][68]
    float* sk = sq + 64 * 68;        // [64][68]
    float* sp = sk + 64 * 68;        // [64][68]
    float* sv = sp + 64 * 68;        // [64][72]

    const int qt = blockIdx.x, h = blockIdx.y, b = blockIdx.z;
    const int tid = threadIdx.x;
    const int lane = tid & 31;
    const int warp = tid >> 5;
    const int g = lane >> 2;
    const int tg = lane & 3;
    const int w16 = warp * 16;
    const int q0 = qt * 64;
    const size_t base = (size_t)b * S_LEN * DMODEL + (size_t)h * DKH;

    {
        const int r = tid >> 1;
        const int cb = (tid & 1) * 32;
        const float* src = Q + base + (size_t)(q0 + r) * DMODEL + cb;
        float* dst = sq + r * 68 + cb;
        #pragma unroll
        for (int i = 0; i < 8; i++)
            *(float4*)(dst + i * 4) = *(const float4*)(src + i * 4);
    }

    float m0 = -1e30f, m1 = -1e30f, l0 = 0.f, l1 = 0.f;
    float oacc[8][4];
    #pragma unroll
    for (int n = 0; n < 8; n++)
        #pragma unroll
        for (int c = 0; c < 4; c++) oacc[n][c] = 0.f;

    for (int kt = 0; kt < S_LEN / 64; kt++) {
        const int j0 = kt * 64;
        __syncthreads();
        {
            const int r = tid >> 1;
            const int cb = (tid & 1) * 32;
            const float* srck = Kg + base + (size_t)(j0 + r) * DMODEL + cb;
            const float* srcv = Vg + base + (size_t)(j0 + r) * DMODEL + cb;
            float* dk = sk + r * 68 + cb;
            float* dv = sv + r * 72 + cb;
            #pragma unroll
            for (int i = 0; i < 8; i++) {
                *(float4*)(dk + i * 4) = *(const float4*)(srck + i * 4);
                *(float4*)(dv + i * 4) = *(const float4*)(srcv + i * 4);
            }
        }
        __syncthreads();

        float sacc[8][4];
        #pragma unroll
        for (int n = 0; n < 8; n++)
            #pragma unroll
            for (int c = 0; c < 4; c++) sacc[n][c] = 0.f;

        #pragma unroll
        for (int k8 = 0; k8 < 8; k8++) {
            const int c = k8 * 8 + tg;
            unsigned a[4];
            a[0] = __float_as_uint(sq[(w16 + g) * 68 + c]);
            a[1] = __float_as_uint(sq[(w16 + g + 8) * 68 + c]);
            a[2] = __float_as_uint(sq[(w16 + g) * 68 + c + 4]);
            a[3] = __float_as_uint(sq[(w16 + g + 8) * 68 + c + 4]);
            #pragma unroll
            for (int n = 0; n < 8; n++) {
                unsigned bfr[2];
                bfr[0] = __float_as_uint(sk[(n * 8 + g) * 68 + c]);
                bfr[1] = __float_as_uint(sk[(n * 8 + g) * 68 + c + 4]);
                MMA_TF32(sacc[n], a, bfr);
            }
        }

        float mx0 = -1e30f, mx1 = -1e30f;
        #pragma unroll
        for (int n = 0; n < 8; n++) {
            sacc[n][0] *= 0.125f; sacc[n][1] *= 0.125f;
            sacc[n][2] *= 0.125f; sacc[n][3] *= 0.125f;
            mx0 = fmaxf(mx0, fmaxf(sacc[n][0], sacc[n][1]));
            mx1 = fmaxf(mx1, fmaxf(sacc[n][2], sacc[n][3]));
        }
        mx0 = fmaxf(mx0, __shfl_xor_sync(0xffffffffu, mx0, 1));
        mx0 = fmaxf(mx0, __shfl_xor_sync(0xffffffffu, mx0, 2));
        mx1 = fmaxf(mx1, __shfl_xor_sync(0xffffffffu, mx1, 1));
        mx1 = fmaxf(mx1, __shfl_xor_sync(0xffffffffu, mx1, 2));

        const float mn0 = fmaxf(m0, mx0);
        const float mn1 = fmaxf(m1, mx1);
        const float corr0 = __expf(m0 - mn0);
        const float corr1 = __expf(m1 - mn1);
        float rs0 = 0.f, rs1 = 0.f;
        #pragma unroll
        for (int n = 0; n < 8; n++) {
            float p0 = __expf(sacc[n][0] - mn0);
            float p1 = __expf(sacc[n][1] - mn0);
            float p2 = __expf(sacc[n][2] - mn1);
            float p3 = __expf(sacc[n][3] - mn1);
            rs0 += p0 + p1;
            rs1 += p2 + p3;
            const int col = n * 8 + tg * 2;
            *(float2*)(sp + (w16 + g) * 68 + col)     = make_float2(p0, p1);
            *(float2*)(sp + (w16 + g + 8) * 68 + col) = make_float2(p2, p3);
        }
        rs0 += __shfl_xor_sync(0xffffffffu, rs0, 1);
        rs0 += __shfl_xor_sync(0xffffffffu, rs0, 2);
        rs1 += __shfl_xor_sync(0xffffffffu, rs1, 1);
        rs1 += __shfl_xor_sync(0xffffffffu, rs1, 2);
        l0 = l0 * corr0 + rs0;
        l1 = l1 * corr1 + rs1;
        m0 = mn0; m1 = mn1;
        #pragma unroll
        for (int n = 0; n < 8; n++) {
            oacc[n][0] *= corr0; oacc[n][1] *= corr0;
            oacc[n][2] *= corr1; oacc[n][3] *= corr1;
        }
        __syncwarp();

        #pragma unroll
        for (int k8 = 0; k8 < 8; k8++) {
            const int c = k8 * 8 + tg;
            unsigned a[4];
            a[0] = __float_as_uint(sp[(w16 + g) * 68 + c]);
            a[1] = __float_as_uint(sp[(w16 + g + 8) * 68 + c]);
            a[2] = __float_as_uint(sp[(w16 + g) * 68 + c + 4]);
            a[3] = __float_as_uint(sp[(w16 + g + 8) * 68 + c + 4]);
            #pragma unroll
            for (int n = 0; n < 8; n++) {
                unsigned bfr[2];
                bfr[0] = __float_as_uint(sv[c * 72 + n * 8 + g]);
                bfr[1] = __float_as_uint(sv[(c + 4) * 72 + n * 8 + g]);
                MMA_TF32(oacc[n], a, bfr);
            }
        }
    }

    const float rl0 = 1.f / l0;
    const float rl1 = 1.f / l1;
    float* o0 = O + base + (size_t)(q0 + w16 + g) * DMODEL;
    float* o8 = O + base + (size_t)(q0 + w16 + g + 8) * DMODEL;
    #pragma unroll
    for (int n = 0; n < 8; n++) {
        const int col = n * 8 + tg * 2;
        *(float2*)(o0 + col) = make_float2(oacc[n][0] * rl0, oacc[n][1] * rl0);
        *(float2*)(o8 + col) = make_float2(oacc[n][2] * rl1, oacc[n][3] * rl1);
    }
}

// ---------------- launch ----------------------------------------------------
extern "C" void kernel_launch(void* const* d_in, const int* in_sizes, int n_in,
                              void* d_out, int out_size)
{
    const float* x   = (const float*)d_in[0];
    const float* wq  = (const float*)d_in[2];
    const float* bq  = (const float*)d_in[3];
    const float* wk  = (const float*)d_in[4];
    const float* bk  = (const float*)d_in[5];
    const float* wv  = (const float*)d_in[6];
    const float* bv  = (const float*)d_in[7];
    const float* wo  = (const float*)d_in[8];
    const float* bo  = (const float*)d_in[9];
    const float* w1  = (const float*)d_in[10];
    const float* b1  = (const float*)d_in[11];
    const float* w2  = (const float*)d_in[12];
    const float* b2  = (const float*)d_in[13];
    const float* l1a = (const float*)d_in[14];
    const float* l1b = (const float*)d_in[15];
    const float* l2a = (const float*)d_in[16];
    const float* l2b = (const float*)d_in[17];
    float* out = (float*)d_out;

    float *h, *q, *k, *v, *ctx, *x2, *ffn;
    cudaGetSymbolAddress((void**)&h,   g_h);
    cudaGetSymbolAddress((void**)&q,   g_q);
    cudaGetSymbolAddress((void**)&k,   g_k);
    cudaGetSymbolAddress((void**)&v,   g_v);
    cudaGetSymbolAddress((void**)&ctx, g_ctx);
    cudaGetSymbolAddress((void**)&x2,  g_x2);
    cudaGetSymbolAddress((void**)&ffn, g_ffn);

    cudaFuncSetAttribute(flash_mma, cudaFuncAttributeMaxDynamicSharedMemorySize,
                         FLASH_SMEM_BYTES);
    cudaFuncSetAttribute(mma_gemm_qkv, cudaFuncAttributeMaxDynamicSharedMemorySize,
                         GEMM_SMEM_BYTES);
    cudaFuncSetAttribute(mma_gemm<false, false>, cudaFuncAttributeMaxDynamicSharedMemorySize,
                         GEMM_SMEM_BYTES);
    cudaFuncSetAttribute(mma_gemm<false, true>, cudaFuncAttributeMaxDynamicSharedMemorySize,
                         GEMM_SMEM_BYTES);
    cudaFuncSetAttribute(mma_gemm<true, false>, cudaFuncAttributeMaxDynamicSharedMemorySize,
                         GEMM_SMEM_BYTES);

    const dim3 gProj(DMODEL / 128, NTOK / 128);          // (8, 64)
    const dim3 gQkv (DMODEL / 128, NTOK / 128, 3);       // (8, 64, 3)
    const dim3 gFfn1(DFF / 128,    NTOK / 128);          // (32, 64)

    ln_kernel<<<NTOK, 256>>>(x, h, l1a, l1b);
    mma_gemm_qkv<<<gQkv, 256, GEMM_SMEM_BYTES>>>(h, wq, wk, wv, bq, bk, bv, q, k, v);
    flash_mma<<<dim3(S_LEN / 64, HN, BATCH), 128, FLASH_SMEM_BYTES>>>(q, k, v, ctx);
    mma_gemm<false, true><<<gProj, 256, GEMM_SMEM_BYTES>>>(ctx, wo, bo, x, x2, DMODEL, DMODEL);
    ln_kernel<<<NTOK, 256>>>(x2, h, l2a, l2b);
    mma_gemm<true, false><<<gFfn1, 256, GEMM_SMEM_BYTES>>>(h, w1, b1, nullptr, ffn, DFF, DMODEL);
    mma_gemm<false, true><<<gProj, 256, GEMM_SMEM_BYTES>>>(ffn, w2, b2, x2, out, DMODEL, DFF);
}

// round 14
// speedup vs baseline: 1.0434x; 1.0434x over previous
#include <cuda_runtime.h>
#include <math.h>
#include <stdint.h>

#define S_LEN 2048
#define BATCH 4
#define DMODEL 1024
#define HN 16
#define DKH 64
#define DFF 4096
#define NTOK (BATCH * S_LEN)   // 8192

// ---------------- scratch (static device globals; no runtime allocation) ----
__device__ float g_h  [NTOK * DMODEL];
__device__ float g_q  [NTOK * DMODEL];
__device__ float g_k  [NTOK * DMODEL];
__device__ float g_v  [NTOK * DMODEL];
__device__ float g_ctx[NTOK * DMODEL];
__device__ float g_x2 [NTOK * DMODEL];
__device__ float g_ffn[(size_t)NTOK * DFF];

// ---------------- helpers ----------------------------------------------------
__device__ __forceinline__ unsigned f2tf32(float f) {
    unsigned u;
    asm("cvt.rna.tf32.f32 %0, %1;" : "=r"(u) : "f"(f));
    return u;
}
__device__ __forceinline__ float f2tf32f(float f) {
    return __uint_as_float(f2tf32(f));
}
// cp.async with L1 caching (.ca): A/B slabs are re-read across CTAs, keep them
// in L1. (.cg bypassed L1 and cost ~20% on the GEMM launches.)
__device__ __forceinline__ void cp16(void* s, const void* g) {
    unsigned sa = (unsigned)__cvta_generic_to_shared(s);
    asm volatile("cp.async.ca.shared.global [%0], [%1], 16;" :: "r"(sa), "l"(g));
}
#define CP_COMMIT() asm volatile("cp.async.commit_group;")
#define CP_WAIT0()  asm volatile("cp.async.wait_group 0;")

#define MMA_TF32(d, a, b)                                                     \
    asm volatile(                                                             \
        "mma.sync.aligned.m16n8k8.row.col.f32.tf32.tf32.f32 "                 \
        "{%0,%1,%2,%3},{%4,%5,%6,%7},{%8,%9},{%0,%1,%2,%3};"                  \
        : "+f"((d)[0]), "+f"((d)[1]), "+f"((d)[2]), "+f"((d)[3])              \
        : "r"((a)[0]), "r"((a)[1]), "r"((a)[2]), "r"((a)[3]),                 \
          "r"((b)[0]), "r"((b)[1]))

// ---------------- LayerNorm (torch semantics) --------------------------------
__global__ void ln_kernel(const float* __restrict__ x, float* __restrict__ y,
                          const float* __restrict__ ga, const float* __restrict__ gb)
{
    int row = blockIdx.x;
    const float4* xr = (const float4*)(x + (size_t)row * DMODEL);
    float4* yr = (float4*)(y + (size_t)row * DMODEL);
    int t = threadIdx.x;
    float4 v = xr[t];
    float s  = v.x + v.y + v.z + v.w;
    float ss = v.x*v.x + v.y*v.y + v.z*v.z + v.w*v.w;
    #pragma unroll
    for (int o = 16; o > 0; o >>= 1) {
        s  += __shfl_xor_sync(0xffffffffu, s,  o);
        ss += __shfl_xor_sync(0xffffffffu, ss, o);
    }
    __shared__ float rs[8], rss[8];
    __shared__ float sh_mean, sh_inv, sh_beta;
    int w = t >> 5;
    if ((t & 31) == 0) { rs[w] = s; rss[w] = ss; }
    __syncthreads();
    if (t == 0) {
        float S = 0.f, SS = 0.f;
        #pragma unroll
        for (int i = 0; i < 8; i++) { S += rs[i]; SS += rss[i]; }
        float mean = S / (float)DMODEL;
        float var  = (SS - (float)DMODEL * mean * mean) / (float)(DMODEL - 1);
        var = fmaxf(var, 0.f);
        sh_mean = mean;
        sh_inv  = ga[0] / (sqrtf(var) + 1e-5f);
        sh_beta = gb[0];
    }
    __syncthreads();
    float mean = sh_mean, inv = sh_inv, beta = sh_beta;
    float4 o;
    o.x = (v.x - mean) * inv + beta;
    o.y = (v.y - mean) * inv + beta;
    o.z = (v.z - mean) * inv + beta;
    o.w = (v.w - mean) * inv + beta;
    yr[t] = o;
}

// ---------------- TF32 tensor-core GEMM, cp.async.ca 2-stage -----------------
// C[M,N] = A[M,K] @ W[N,K]^T + bias (+resid)(relu)
// Block 128x128, BK=32, 256 thr = 8 warps (2x4), warp tile 64x32, 2 CTAs/SM.
// Smem row stride 36 -> fragment bank = (4r+c)%32 = lane, conflict-free.
// tf32 conversion (rna) at fragment-load time.
#define GEMM_SMEM_BYTES (2 * 2 * 128 * 36 * 4)

template<bool RELU, bool RESID>
__device__ __forceinline__ void gemm_body(
    const float* __restrict__ A, const float* __restrict__ W,
    const float* __restrict__ bias, const float* __restrict__ resid,
    float* __restrict__ C, int N, int K, int bm, int bn)
{
    extern __shared__ float sm[];
    float* As = sm;                      // [2][128][36]
    float* Bs = sm + 2 * 128 * 36;       // [2][128][36]

    const int tid  = threadIdx.x;
    const int lane = tid & 31;
    const int warp = tid >> 5;
    const int g    = lane >> 2;
    const int tg   = lane & 3;
    const int wm   = (warp >> 2) * 64;
    const int wn   = (warp & 3) * 32;

    // cp.async mapping: 2 threads per row, 16 floats (4x16B) each
    const int lr = tid >> 1;             // 0..127
    const int lc = (tid & 1) * 16;       // 0 or 16
    const float* Ag = A + (size_t)(bm + lr) * K + lc;
    const float* Wg = W + (size_t)(bn + lr) * K + lc;
    float* Asw = As + lr * 36 + lc;
    float* Bsw = Bs + lr * 36 + lc;

    float acc[4][4][4];
    #pragma unroll
    for (int mi = 0; mi < 4; mi++)
        #pragma unroll
        for (int ni = 0; ni < 4; ni++)
            #pragma unroll
            for (int c = 0; c < 4; c++) acc[mi][ni][c] = 0.f;

    // prologue: stage 0 -> buf 0
    #pragma unroll
    for (int i = 0; i < 4; i++) {
        cp16(Asw + i * 4, Ag + i * 4);
        cp16(Bsw + i * 4, Wg + i * 4);
    }
    CP_COMMIT();

    int buf = 0;
    for (int k0 = 0; k0 < K; k0 += 32) {
        CP_WAIT0();
        __syncthreads();    // slab ready + everyone done with prev compute

        if (k0 + 32 < K) {
            const int nb = (buf ^ 1) * 128 * 36;
            #pragma unroll
            for (int i = 0; i < 4; i++) {
                cp16(Asw + nb + i * 4, Ag + k0 + 32 + i * 4);
                cp16(Bsw + nb + i * 4, Wg + k0 + 32 + i * 4);
            }
            CP_COMMIT();
        }

        const float* Ab = As + buf * 128 * 36;
        const float* Bb = Bs + buf * 128 * 36;
        #pragma unroll
        for (int ks = 0; ks < 4; ks++) {
            unsigned a[4][4], b[4][2];
            const int c = ks * 8 + tg;
            #pragma unroll
            for (int mi = 0; mi < 4; mi++) {
                const int r = wm + mi * 16 + g;
                a[mi][0] = f2tf32(Ab[r * 36 + c]);
                a[mi][1] = f2tf32(Ab[(r + 8) * 36 + c]);
                a[mi][2] = f2tf32(Ab[r * 36 + c + 4]);
                a[mi][3] = f2tf32(Ab[(r + 8) * 36 + c + 4]);
            }
            #pragma unroll
            for (int ni = 0; ni < 4; ni++) {
                const int r = wn + ni * 8 + g;
                b[ni][0] = f2tf32(Bb[r * 36 + c]);
                b[ni][1] = f2tf32(Bb[r * 36 + c + 4]);
            }
            #pragma unroll
            for (int mi = 0; mi < 4; mi++)
                #pragma unroll
                for (int ni = 0; ni < 4; ni++)
                    MMA_TF32(acc[mi][ni], a[mi], b[ni]);
        }
        buf ^= 1;
    }

    // epilogue
    #pragma unroll
    for (int mi = 0; mi < 4; mi++) {
        int row0 = bm + wm + mi * 16 + g;
        #pragma unroll
        for (int ni = 0; ni < 4; ni++) {
            int col = bn + wn + ni * 8 + tg * 2;
            float bia0 = bias[col], bia1 = bias[col + 1];
            float v0 = acc[mi][ni][0] + bia0;
            float v1 = acc[mi][ni][1] + bia1;
            float v2 = acc[mi][ni][2] + bia0;
            float v3 = acc[mi][ni][3] + bia1;
            if (RESID) {
                const float* r0 = resid + (size_t)row0 * N + col;
                const float* r8 = resid + (size_t)(row0 + 8) * N + col;
                v0 += r0[0]; v1 += r0[1];
                v2 += r8[0]; v3 += r8[1];
            }
            if (RELU) {
                v0 = fmaxf(v0, 0.f); v1 = fmaxf(v1, 0.f);
                v2 = fmaxf(v2, 0.f); v3 = fmaxf(v3, 0.f);
            }
            *(float2*)(C + (size_t)row0 * N + col)       = make_float2(v0, v1);
            *(float2*)(C + (size_t)(row0 + 8) * N + col) = make_float2(v2, v3);
        }
    }
}

template<bool RELU, bool RESID>
__global__ void __launch_bounds__(256, 2) mma_gemm(
    const float* __restrict__ A, const float* __restrict__ W,
    const float* __restrict__ bias, const float* __restrict__ resid,
    float* __restrict__ C, int N, int K)
{
    gemm_body<RELU, RESID>(A, W, bias, resid, C, N, K,
                           blockIdx.y * 128, blockIdx.x * 128);
}

// merged QKV: blockIdx.z selects weight/bias/output
__global__ void __launch_bounds__(256, 2) mma_gemm_qkv(
    const float* __restrict__ A,
    const float* __restrict__ wq, const float* __restrict__ wk, const float* __restrict__ wv,
    const float* __restrict__ bq, const float* __restrict__ bk, const float* __restrict__ bv,
    float* __restrict__ oq, float* __restrict__ ok, float* __restrict__ ov)
{
    const int z = blockIdx.z;
    const float* W = (z == 0) ? wq : (z == 1) ? wk : wv;
    const float* B = (z == 0) ? bq : (z == 1) ? bk : bv;
    float*       C = (z == 0) ? oq : (z == 1) ? ok : ov;
    gemm_body<false, false>(A, W, B, nullptr, C, DMODEL, DMODEL,
                            blockIdx.y * 128, blockIdx.x * 128);
}

// ---------------- Flash attention on tf32 tensor cores -----------------------
// Br=64, Bc=64, 4 warps; rna-converted tf32 operands (accuracy).
#define FLASH_SMEM_BYTES ((64 * 68 * 3 + 64 * 72) * 4)

__global__ void __launch_bounds__(128) flash_mma(
    const float* __restrict__ Q, const float* __restrict__ Kg,
    const float* __restrict__ Vg, float* __restrict__ O)
{
    extern __shared__ float fsm[];
    float* sq = fsm;                 // [64][68]
    float* sk = sq + 64 * 68;        // [64][68]
    float* sp = sk + 64 * 68;        // [64][68]
    float* sv = sp + 64 * 68;        // [64][72]

    const int qt = blockIdx.x, h = blockIdx.y, b = blockIdx.z;
    const int tid = threadIdx.x;
    const int lane = tid & 31;
    const int warp = tid >> 5;
    const int g = lane >> 2;
    const int tg = lane & 3;
    const int w16 = warp * 16;
    const int q0 = qt * 64;
    const size_t base = (size_t)b * S_LEN * DMODEL + (size_t)h * DKH;

    {
        const int r = tid >> 1;
        const int cb = (tid & 1) * 32;
        const float* src = Q + base + (size_t)(q0 + r) * DMODEL + cb;
        float* dst = sq + r * 68 + cb;
        #pragma unroll
        for (int i = 0; i < 8; i++) {
            float4 v = *(const float4*)(src + i * 4);
            v.x = f2tf32f(v.x); v.y = f2tf32f(v.y);
            v.z = f2tf32f(v.z); v.w = f2tf32f(v.w);
            *(float4*)(dst + i * 4) = v;
        }
    }

    float m0 = -1e30f, m1 = -1e30f, l0 = 0.f, l1 = 0.f;
    float oacc[8][4];
    #pragma unroll
    for (int n = 0; n < 8; n++)
        #pragma unroll
        for (int c = 0; c < 4; c++) oacc[n][c] = 0.f;

    for (int kt = 0; kt < S_LEN / 64; kt++) {
        const int j0 = kt * 64;
        __syncthreads();
        {
            const int r = tid >> 1;
            const int cb = (tid & 1) * 32;
            const float* srck = Kg + base + (size_t)(j0 + r) * DMODEL + cb;
            const float* srcv = Vg + base + (size_t)(j0 + r) * DMODEL + cb;
            float* dk = sk + r * 68 + cb;
            float* dv = sv + r * 72 + cb;
            #pragma unroll
            for (int i = 0; i < 8; i++) {
                float4 kv = *(const float4*)(srck + i * 4);
                float4 vv = *(const float4*)(srcv + i * 4);
                kv.x = f2tf32f(kv.x); kv.y = f2tf32f(kv.y);
                kv.z = f2tf32f(kv.z); kv.w = f2tf32f(kv.w);
                vv.x = f2tf32f(vv.x); vv.y = f2tf32f(vv.y);
                vv.z = f2tf32f(vv.z); vv.w = f2tf32f(vv.w);
                *(float4*)(dk + i * 4) = kv;
                *(float4*)(dv + i * 4) = vv;
            }
        }
        __syncthreads();

        float sacc[8][4];
        #pragma unroll
        for (int n = 0; n < 8; n++)
            #pragma unroll
            for (int c = 0; c < 4; c++) sacc[n][c] = 0.f;

        #pragma unroll
        for (int k8 = 0; k8 < 8; k8++) {
            const int c = k8 * 8 + tg;
            unsigned a[4];
            a[0] = __float_as_uint(sq[(w16 + g) * 68 + c]);
            a[1] = __float_as_uint(sq[(w16 + g + 8) * 68 + c]);
            a[2] = __float_as_uint(sq[(w16 + g) * 68 + c + 4]);
            a[3] = __float_as_uint(sq[(w16 + g + 8) * 68 + c + 4]);
            #pragma unroll
            for (int n = 0; n < 8; n++) {
                unsigned bfr[2];
                bfr[0] = __float_as_uint(sk[(n * 8 + g) * 68 + c]);
                bfr[1] = __float_as_uint(sk[(n * 8 + g) * 68 + c + 4]);
                MMA_TF32(sacc[n], a, bfr);
            }
        }

        float mx0 = -1e30f, mx1 = -1e30f;
        #pragma unroll
        for (int n = 0; n < 8; n++) {
            sacc[n][0] *= 0.125f; sacc[n][1] *= 0.125f;
            sacc[n][2] *= 0.125f; sacc[n][3] *= 0.125f;
            mx0 = fmaxf(mx0, fmaxf(sacc[n][0], sacc[n][1]));
            mx1 = fmaxf(mx1, fmaxf(sacc[n][2], sacc[n][3]));
        }
        mx0 = fmaxf(mx0, __shfl_xor_sync(0xffffffffu, mx0, 1));
        mx0 = fmaxf(mx0, __shfl_xor_sync(0xffffffffu, mx0, 2));
        mx1 = fmaxf(mx1, __shfl_xor_sync(0xffffffffu, mx1, 1));
        mx1 = fmaxf(mx1, __shfl_xor_sync(0xffffffffu, mx1, 2));

        const float mn0 = fmaxf(m0, mx0);
        const float mn1 = fmaxf(m1, mx1);
        const float corr0 = __expf(m0 - mn0);
        const float corr1 = __expf(m1 - mn1);
        float rs0 = 0.f, rs1 = 0.f;
        #pragma unroll
        for (int n = 0; n < 8; n++) {
            float p0 = __expf(sacc[n][0] - mn0);
            float p1 = __expf(sacc[n][1] - mn0);
            float p2 = __expf(sacc[n][2] - mn1);
            float p3 = __expf(sacc[n][3] - mn1);
            rs0 += p0 + p1;
            rs1 += p2 + p3;
            const int col = n * 8 + tg * 2;
            *(float2*)(sp + (w16 + g) * 68 + col) =
                make_float2(f2tf32f(p0), f2tf32f(p1));
            *(float2*)(sp + (w16 + g + 8) * 68 + col) =
                make_float2(f2tf32f(p2), f2tf32f(p3));
        }
        rs0 += __shfl_xor_sync(0xffffffffu, rs0, 1);
        rs0 += __shfl_xor_sync(0xffffffffu, rs0, 2);
        rs1 += __shfl_xor_sync(0xffffffffu, rs1, 1);
        rs1 += __shfl_xor_sync(0xffffffffu, rs1, 2);
        l0 = l0 * corr0 + rs0;
        l1 = l1 * corr1 + rs1;
        m0 = mn0; m1 = mn1;
        #pragma unroll
        for (int n = 0; n < 8; n++) {
            oacc[n][0] *= corr0; oacc[n][1] *= corr0;
            oacc[n][2] *= corr1; oacc[n][3] *= corr1;
        }
        __syncwarp();

        #pragma unroll
        for (int k8 = 0; k8 < 8; k8++) {
            const int c = k8 * 8 + tg;
            unsigned a[4];
            a[0] = __float_as_uint(sp[(w16 + g) * 68 + c]);
            a[1] = __float_as_uint(sp[(w16 + g + 8) * 68 + c]);
            a[2] = __float_as_uint(sp[(w16 + g) * 68 + c + 4]);
            a[3] = __float_as_uint(sp[(w16 + g + 8) * 68 + c + 4]);
            #pragma unroll
            for (int n = 0; n < 8; n++) {
                unsigned bfr[2];
                bfr[0] = __float_as_uint(sv[c * 72 + n * 8 + g]);
                bfr[1] = __float_as_uint(sv[(c + 4) * 72 + n * 8 + g]);
                MMA_TF32(oacc[n], a, bfr);
            }
        }
    }

    const float rl0 = 1.f / l0;
    const float rl1 = 1.f / l1;
    float* o0 = O + base + (size_t)(q0 + w16 + g) * DMODEL;
    float* o8 = O + base + (size_t)(q0 + w16 + g + 8) * DMODEL;
    #pragma unroll
    for (int n = 0; n < 8; n++) {
        const int col = n * 8 + tg * 2;
        *(float2*)(o0 + col) = make_float2(oacc[n][0] * rl0, oacc[n][1] * rl0);
        *(float2*)(o8 + col) = make_float2(oacc[n][2] * rl1, oacc[n][3] * rl1);
    }
}

// ---------------- launch ----------------------------------------------------
extern "C" void kernel_launch(void* const* d_in, const int* in_sizes, int n_in,
                              void* d_out, int out_size)
{
    const float* x   = (const float*)d_in[0];
    const float* wq  = (const float*)d_in[2];
    const float* bq  = (const float*)d_in[3];
    const float* wk  = (const float*)d_in[4];
    const float* bk  = (const float*)d_in[5];
    const float* wv  = (const float*)d_in[6];
    const float* bv  = (const float*)d_in[7];
    const float* wo  = (const float*)d_in[8];
    const float* bo  = (const float*)d_in[9];
    const float* w1  = (const float*)d_in[10];
    const float* b1  = (const float*)d_in[11];
    const float* w2  = (const float*)d_in[12];
    const float* b2  = (const float*)d_in[13];
    const float* l1a = (const float*)d_in[14];
    const float* l1b = (const float*)d_in[15];
    const float* l2a = (const float*)d_in[16];
    const float* l2b = (const float*)d_in[17];
    float* out = (float*)d_out;

    float *h, *q, *k, *v, *ctx, *x2, *ffn;
    cudaGetSymbolAddress((void**)&h,   g_h);
    cudaGetSymbolAddress((void**)&q,   g_q);
    cudaGetSymbolAddress((void**)&k,   g_k);
    cudaGetSymbolAddress((void**)&v,   g_v);
    cudaGetSymbolAddress((void**)&ctx, g_ctx);
    cudaGetSymbolAddress((void**)&x2,  g_x2);
    cudaGetSymbolAddress((void**)&ffn, g_ffn);

    cudaFuncSetAttribute(flash_mma, cudaFuncAttributeMaxDynamicSharedMemorySize,
                         FLASH_SMEM_BYTES);
    cudaFuncSetAttribute(mma_gemm_qkv, cudaFuncAttributeMaxDynamicSharedMemorySize,
                         GEMM_SMEM_BYTES);
    cudaFuncSetAttribute(mma_gemm<false, false>, cudaFuncAttributeMaxDynamicSharedMemorySize,
                         GEMM_SMEM_BYTES);
    cudaFuncSetAttribute(mma_gemm<false, true>, cudaFuncAttributeMaxDynamicSharedMemorySize,
                         GEMM_SMEM_BYTES);
    cudaFuncSetAttribute(mma_gemm<true, false>, cudaFuncAttributeMaxDynamicSharedMemorySize,
                         GEMM_SMEM_BYTES);

    const dim3 gProj(DMODEL / 128, NTOK / 128);          // (8, 64)
    const dim3 gQkv (DMODEL / 128, NTOK / 128, 3);       // (8, 64, 3)
    const dim3 gFfn1(DFF / 128,    NTOK / 128);          // (32, 64)

    ln_kernel<<<NTOK, 256>>>(x, h, l1a, l1b);
    mma_gemm_qkv<<<gQkv, 256, GEMM_SMEM_BYTES>>>(h, wq, wk, wv, bq, bk, bv, q, k, v);
    flash_mma<<<dim3(S_LEN / 64, HN, BATCH), 128, FLASH_SMEM_BYTES>>>(q, k, v, ctx);
    mma_gemm<false, true><<<gProj, 256, GEMM_SMEM_BYTES>>>(ctx, wo, bo, x, x2, DMODEL, DMODEL);
    ln_kernel<<<NTOK, 256>>>(x2, h, l2a, l2b);
    mma_gemm<true, false><<<gFfn1, 256, GEMM_SMEM_BYTES>>>(h, w1, b1, nullptr, ffn, DFF, DMODEL);
    mma_gemm<false, true><<<gProj, 256, GEMM_SMEM_BYTES>>>(ffn, w2, b2, x2, out, DMODEL, DFF);
}

// round 15
// speedup vs baseline: 1.1889x; 1.1395x over previous
#include <cuda_runtime.h>
#include <math.h>
#include <stdint.h>

#define S_LEN 2048
#define BATCH 4
#define DMODEL 1024
#define HN 16
#define DKH 64
#define DFF 4096
#define NTOK (BATCH * S_LEN)   // 8192

// ---------------- scratch (static device globals; no runtime allocation) ----
__device__ float g_h  [NTOK * DMODEL];
__device__ float g_q  [NTOK * DMODEL];
__device__ float g_k  [NTOK * DMODEL];
__device__ float g_v  [NTOK * DMODEL];
__device__ float g_ctx[NTOK * DMODEL];
__device__ float g_x2 [NTOK * DMODEL];
__device__ float g_ffn[(size_t)NTOK * DFF];

// ---------------- helpers ----------------------------------------------------
__device__ __forceinline__ unsigned f2tf32(float f) {
    unsigned u;
    asm("cvt.rna.tf32.f32 %0, %1;" : "=r"(u) : "f"(f));
    return u;
}
__device__ __forceinline__ float f2tf32f(float f) {
    return __uint_as_float(f2tf32(f));
}
__device__ __forceinline__ void cp16(void* s, const void* g) {
    unsigned sa = (unsigned)__cvta_generic_to_shared(s);
    asm volatile("cp.async.ca.shared.global [%0], [%1], 16;" :: "r"(sa), "l"(g));
}
#define CP_COMMIT() asm volatile("cp.async.commit_group;")
#define CP_WAIT0()  asm volatile("cp.async.wait_group 0;")

#define MMA_TF32(d, a, b)                                                     \
    asm volatile(                                                             \
        "mma.sync.aligned.m16n8k8.row.col.f32.tf32.tf32.f32 "                 \
        "{%0,%1,%2,%3},{%4,%5,%6,%7},{%8,%9},{%0,%1,%2,%3};"                  \
        : "+f"((d)[0]), "+f"((d)[1]), "+f"((d)[2]), "+f"((d)[3])              \
        : "r"((a)[0]), "r"((a)[1]), "r"((a)[2]), "r"((a)[3]),                 \
          "r"((b)[0]), "r"((b)[1]))

// ---------------- LayerNorm (torch semantics) --------------------------------
__global__ void ln_kernel(const float* __restrict__ x, float* __restrict__ y,
                          const float* __restrict__ ga, const float* __restrict__ gb)
{
    int row = blockIdx.x;
    const float4* xr = (const float4*)(x + (size_t)row * DMODEL);
    float4* yr = (float4*)(y + (size_t)row * DMODEL);
    int t = threadIdx.x;
    float4 v = xr[t];
    float s  = v.x + v.y + v.z + v.w;
    float ss = v.x*v.x + v.y*v.y + v.z*v.z + v.w*v.w;
    #pragma unroll
    for (int o = 16; o > 0; o >>= 1) {
        s  += __shfl_xor_sync(0xffffffffu, s,  o);
        ss += __shfl_xor_sync(0xffffffffu, ss, o);
    }
    __shared__ float rs[8], rss[8];
    __shared__ float sh_mean, sh_inv, sh_beta;
    int w = t >> 5;
    if ((t & 31) == 0) { rs[w] = s; rss[w] = ss; }
    __syncthreads();
    if (t == 0) {
        float S = 0.f, SS = 0.f;
        #pragma unroll
        for (int i = 0; i < 8; i++) { S += rs[i]; SS += rss[i]; }
        float mean = S / (float)DMODEL;
        float var  = (SS - (float)DMODEL * mean * mean) / (float)(DMODEL - 1);
        var = fmaxf(var, 0.f);
        sh_mean = mean;
        sh_inv  = ga[0] / (sqrtf(var) + 1e-5f);
        sh_beta = gb[0];
    }
    __syncthreads();
    float mean = sh_mean, inv = sh_inv, beta = sh_beta;
    float4 o;
    o.x = (v.x - mean) * inv + beta;
    o.y = (v.y - mean) * inv + beta;
    o.z = (v.z - mean) * inv + beta;
    o.w = (v.w - mean) * inv + beta;
    yr[t] = o;
}

// ---------------- TF32 tensor-core GEMM: 128x256 tile, warp 64x64 ------------
// C[M,N] = A[M,K] @ W[N,K]^T + bias (+resid)(relu)
// Block tile 128(M)x256(N), BK=32, 2-stage cp.async, 256 thr = 8 warps (2x4),
// warp tile 64x64 -> 32 HMMA per 32 fragment LDS (1.0 LDS/HMMA), occ 1.
// Smem row stride 36 -> conflict-free fragment loads.
#define GEMM_SMEM_BYTES ((2 * 128 * 36 + 2 * 256 * 36) * 4)   // 110592

template<bool RELU, bool RESID>
__device__ __forceinline__ void gemm_body(
    const float* __restrict__ A, const float* __restrict__ W,
    const float* __restrict__ bias, const float* __restrict__ resid,
    float* __restrict__ C, int N, int K, int bm, int bn)
{
    extern __shared__ float sm[];
    float* As = sm;                      // [2][128][36]
    float* Bs = sm + 2 * 128 * 36;       // [2][256][36]

    const int tid  = threadIdx.x;
    const int lane = tid & 31;
    const int warp = tid >> 5;
    const int g    = lane >> 2;
    const int tg   = lane & 3;
    const int wm   = (warp >> 2) * 64;   // 0, 64
    const int wn   = (warp & 3) * 64;    // 0, 64, 128, 192

    // cp.async mapping
    // A: 128 rows x 32 floats: 2 threads/row, 16 floats (4 cp16) each
    const int lrA = tid >> 1;
    const int lcA = (tid & 1) * 16;
    const float* Ag = A + (size_t)(bm + lrA) * K + lcA;
    float* Asw = As + lrA * 36 + lcA;
    // B: 256 rows x 32 floats: 1 thread/row, 32 floats (8 cp16) each
    const float* Wg = W + (size_t)(bn + tid) * K;
    float* Bsw = Bs + tid * 36;

    float acc[4][8][4];
    #pragma unroll
    for (int mi = 0; mi < 4; mi++)
        #pragma unroll
        for (int ni = 0; ni < 8; ni++)
            #pragma unroll
            for (int c = 0; c < 4; c++) acc[mi][ni][c] = 0.f;

    // prologue: stage slab 0 -> buf 0
    #pragma unroll
    for (int i = 0; i < 4; i++) cp16(Asw + i * 4, Ag + i * 4);
    #pragma unroll
    for (int i = 0; i < 8; i++) cp16(Bsw + i * 4, Wg + i * 4);
    CP_COMMIT();

    int buf = 0;
    for (int k0 = 0; k0 < K; k0 += 32) {
        CP_WAIT0();
        __syncthreads();

        if (k0 + 32 < K) {
            const int nbA = (buf ^ 1) * 128 * 36;
            const int nbB = (buf ^ 1) * 256 * 36;
            #pragma unroll
            for (int i = 0; i < 4; i++) cp16(Asw + nbA + i * 4, Ag + k0 + 32 + i * 4);
            #pragma unroll
            for (int i = 0; i < 8; i++) cp16(Bsw + nbB + i * 4, Wg + k0 + 32 + i * 4);
            CP_COMMIT();
        }

        const float* Ab = As + buf * 128 * 36;
        const float* Bb = Bs + buf * 256 * 36;
        #pragma unroll
        for (int ks = 0; ks < 4; ks++) {
            unsigned a[4][4], b[8][2];
            const int c = ks * 8 + tg;
            #pragma unroll
            for (int mi = 0; mi < 4; mi++) {
                const int r = wm + mi * 16 + g;
                a[mi][0] = f2tf32(Ab[r * 36 + c]);
                a[mi][1] = f2tf32(Ab[(r + 8) * 36 + c]);
                a[mi][2] = f2tf32(Ab[r * 36 + c + 4]);
                a[mi][3] = f2tf32(Ab[(r + 8) * 36 + c + 4]);
            }
            #pragma unroll
            for (int ni = 0; ni < 8; ni++) {
                const int r = wn + ni * 8 + g;
                b[ni][0] = f2tf32(Bb[r * 36 + c]);
                b[ni][1] = f2tf32(Bb[r * 36 + c + 4]);
            }
            #pragma unroll
            for (int mi = 0; mi < 4; mi++)
                #pragma unroll
                for (int ni = 0; ni < 8; ni++)
                    MMA_TF32(acc[mi][ni], a[mi], b[ni]);
        }
        buf ^= 1;
    }

    // epilogue
    #pragma unroll
    for (int mi = 0; mi < 4; mi++) {
        int row0 = bm + wm + mi * 16 + g;
        #pragma unroll
        for (int ni = 0; ni < 8; ni++) {
            int col = bn + wn + ni * 8 + tg * 2;
            float bia0 = bias[col], bia1 = bias[col + 1];
            float v0 = acc[mi][ni][0] + bia0;
            float v1 = acc[mi][ni][1] + bia1;
            float v2 = acc[mi][ni][2] + bia0;
            float v3 = acc[mi][ni][3] + bia1;
            if (RESID) {
                const float* r0 = resid + (size_t)row0 * N + col;
                const float* r8 = resid + (size_t)(row0 + 8) * N + col;
                v0 += r0[0]; v1 += r0[1];
                v2 += r8[0]; v3 += r8[1];
            }
            if (RELU) {
                v0 = fmaxf(v0, 0.f); v1 = fmaxf(v1, 0.f);
                v2 = fmaxf(v2, 0.f); v3 = fmaxf(v3, 0.f);
            }
            *(float2*)(C + (size_t)row0 * N + col)       = make_float2(v0, v1);
            *(float2*)(C + (size_t)(row0 + 8) * N + col) = make_float2(v2, v3);
        }
    }
}

template<bool RELU, bool RESID>
__global__ void __launch_bounds__(256, 1) mma_gemm(
    const float* __restrict__ A, const float* __restrict__ W,
    const float* __restrict__ bias, const float* __restrict__ resid,
    float* __restrict__ C, int N, int K)
{
    gemm_body<RELU, RESID>(A, W, bias, resid, C, N, K,
                           blockIdx.y * 128, blockIdx.x * 256);
}

// merged QKV: blockIdx.z selects weight/bias/output
__global__ void __launch_bounds__(256, 1) mma_gemm_qkv(
    const float* __restrict__ A,
    const float* __restrict__ wq, const float* __restrict__ wk, const float* __restrict__ wv,
    const float* __restrict__ bq, const float* __restrict__ bk, const float* __restrict__ bv,
    float* __restrict__ oq, float* __restrict__ ok, float* __restrict__ ov)
{
    const int z = blockIdx.z;
    const float* W = (z == 0) ? wq : (z == 1) ? wk : wv;
    const float* B = (z == 0) ? bq : (z == 1) ? bk : bv;
    float*       C = (z == 0) ? oq : (z == 1) ? ok : ov;
    gemm_body<false, false>(A, W, B, nullptr, C, DMODEL, DMODEL,
                            blockIdx.y * 128, blockIdx.x * 256);
}

// ---------------- Flash attention: Br=128, Bc=64, 8 warps --------------------
// Warp owns 16 query rows (same per-warp design); K/V loads and barriers
// amortized over 2x queries vs Br=64. Pads: 68 (Q/K/P), 72 (V).
#define FLASH_SMEM_BYTES ((128 * 68 + 64 * 68 + 128 * 68 + 64 * 72) * 4)  // 105472

__global__ void __launch_bounds__(256) flash_mma(
    const float* __restrict__ Q, const float* __restrict__ Kg,
    const float* __restrict__ Vg, float* __restrict__ O)
{
    extern __shared__ float fsm[];
    float* sq = fsm;                   // [128][68]
    float* sk = sq + 128 * 68;         // [64][68]
    float* sp = sk + 64 * 68;          // [128][68]
    float* sv = sp + 128 * 68;         // [64][72]

    const int qt = blockIdx.x, h = blockIdx.y, b = blockIdx.z;
    const int tid = threadIdx.x;
    const int lane = tid & 31;
    const int warp = tid >> 5;         // 0..7
    const int g = lane >> 2;
    const int tg = lane & 3;
    const int w16 = warp * 16;
    const int q0 = qt * 128;
    const size_t base = (size_t)b * S_LEN * DMODEL + (size_t)h * DKH;

    // load Q tile (tf32): 128 rows x 64 cols; 2 threads/row, 8 float4 each
    {
        const int r = tid >> 1;
        const int cb = (tid & 1) * 32;
        const float* src = Q + base + (size_t)(q0 + r) * DMODEL + cb;
        float* dst = sq + r * 68 + cb;
        #pragma unroll
        for (int i = 0; i < 8; i++) {
            float4 v = *(const float4*)(src + i * 4);
            v.x = f2tf32f(v.x); v.y = f2tf32f(v.y);
            v.z = f2tf32f(v.z); v.w = f2tf32f(v.w);
            *(float4*)(dst + i * 4) = v;
        }
    }

    float m0 = -1e30f, m1 = -1e30f, l0 = 0.f, l1 = 0.f;
    float oacc[8][4];
    #pragma unroll
    for (int n = 0; n < 8; n++)
        #pragma unroll
        for (int c = 0; c < 4; c++) oacc[n][c] = 0.f;

    for (int kt = 0; kt < S_LEN / 64; kt++) {
        const int j0 = kt * 64;
        __syncthreads();   // previous PV done before overwriting K/V
        // K/V: 64 rows x 64 cols; 4 threads/row, 4 float4 each
        {
            const int r = tid >> 2;
            const int cb = (tid & 3) * 16;
            const float* srck = Kg + base + (size_t)(j0 + r) * DMODEL + cb;
            const float* srcv = Vg + base + (size_t)(j0 + r) * DMODEL + cb;
            float* dk = sk + r * 68 + cb;
            float* dv = sv + r * 72 + cb;
            #pragma unroll
            for (int i = 0; i < 4; i++) {
                float4 kv = *(const float4*)(srck + i * 4);
                float4 vv = *(const float4*)(srcv + i * 4);
                kv.x = f2tf32f(kv.x); kv.y = f2tf32f(kv.y);
                kv.z = f2tf32f(kv.z); kv.w = f2tf32f(kv.w);
                vv.x = f2tf32f(vv.x); vv.y = f2tf32f(vv.y);
                vv.z = f2tf32f(vv.z); vv.w = f2tf32f(vv.w);
                *(float4*)(dk + i * 4) = kv;
                *(float4*)(dv + i * 4) = vv;
            }
        }
        __syncthreads();

        // ---- S = Q.K^T (warp: 16 rows x 64 kv) ----
        float sacc[8][4];
        #pragma unroll
        for (int n = 0; n < 8; n++)
            #pragma unroll
            for (int c = 0; c < 4; c++) sacc[n][c] = 0.f;

        #pragma unroll
        for (int k8 = 0; k8 < 8; k8++) {
            const int c = k8 * 8 + tg;
            unsigned a[4];
            a[0] = __float_as_uint(sq[(w16 + g) * 68 + c]);
            a[1] = __float_as_uint(sq[(w16 + g + 8) * 68 + c]);
            a[2] = __float_as_uint(sq[(w16 + g) * 68 + c + 4]);
            a[3] = __float_as_uint(sq[(w16 + g + 8) * 68 + c + 4]);
            #pragma unroll
            for (int n = 0; n < 8; n++) {
                unsigned bfr[2];
                bfr[0] = __float_as_uint(sk[(n * 8 + g) * 68 + c]);
                bfr[1] = __float_as_uint(sk[(n * 8 + g) * 68 + c + 4]);
                MMA_TF32(sacc[n], a, bfr);
            }
        }

        // ---- online softmax on fragments (rows g and g+8 of warp tile) ----
        float mx0 = -1e30f, mx1 = -1e30f;
        #pragma unroll
        for (int n = 0; n < 8; n++) {
            sacc[n][0] *= 0.125f; sacc[n][1] *= 0.125f;
            sacc[n][2] *= 0.125f; sacc[n][3] *= 0.125f;
            mx0 = fmaxf(mx0, fmaxf(sacc[n][0], sacc[n][1]));
            mx1 = fmaxf(mx1, fmaxf(sacc[n][2], sacc[n][3]));
        }
        mx0 = fmaxf(mx0, __shfl_xor_sync(0xffffffffu, mx0, 1));
        mx0 = fmaxf(mx0, __shfl_xor_sync(0xffffffffu, mx0, 2));
        mx1 = fmaxf(mx1, __shfl_xor_sync(0xffffffffu, mx1, 1));
        mx1 = fmaxf(mx1, __shfl_xor_sync(0xffffffffu, mx1, 2));

        const float mn0 = fmaxf(m0, mx0);
        const float mn1 = fmaxf(m1, mx1);
        const float corr0 = __expf(m0 - mn0);
        const float corr1 = __expf(m1 - mn1);
        float rs0 = 0.f, rs1 = 0.f;
        #pragma unroll
        for (int n = 0; n < 8; n++) {
            float p0 = __expf(sacc[n][0] - mn0);
            float p1 = __expf(sacc[n][1] - mn0);
            float p2 = __expf(sacc[n][2] - mn1);
            float p3 = __expf(sacc[n][3] - mn1);
            rs0 += p0 + p1;
            rs1 += p2 + p3;
            const int col = n * 8 + tg * 2;
            *(float2*)(sp + (w16 + g) * 68 + col) =
                make_float2(f2tf32f(p0), f2tf32f(p1));
            *(float2*)(sp + (w16 + g + 8) * 68 + col) =
                make_float2(f2tf32f(p2), f2tf32f(p3));
        }
        rs0 += __shfl_xor_sync(0xffffffffu, rs0, 1);
        rs0 += __shfl_xor_sync(0xffffffffu, rs0, 2);
        rs1 += __shfl_xor_sync(0xffffffffu, rs1, 1);
        rs1 += __shfl_xor_sync(0xffffffffu, rs1, 2);
        l0 = l0 * corr0 + rs0;
        l1 = l1 * corr1 + rs1;
        m0 = mn0; m1 = mn1;
        #pragma unroll
        for (int n = 0; n < 8; n++) {
            oacc[n][0] *= corr0; oacc[n][1] *= corr0;
            oacc[n][2] *= corr1; oacc[n][3] *= corr1;
        }
        __syncwarp();   // P rows are warp-private

        // ---- O += P.V ----
        #pragma unroll
        for (int k8 = 0; k8 < 8; k8++) {
            const int c = k8 * 8 + tg;
            unsigned a[4];
            a[0] = __float_as_uint(sp[(w16 + g) * 68 + c]);
            a[1] = __float_as_uint(sp[(w16 + g + 8) * 68 + c]);
            a[2] = __float_as_uint(sp[(w16 + g) * 68 + c + 4]);
            a[3] = __float_as_uint(sp[(w16 + g + 8) * 68 + c + 4]);
            #pragma unroll
            for (int n = 0; n < 8; n++) {
                unsigned bfr[2];
                bfr[0] = __float_as_uint(sv[c * 72 + n * 8 + g]);
                bfr[1] = __float_as_uint(sv[(c + 4) * 72 + n * 8 + g]);
                MMA_TF32(oacc[n], a, bfr);
            }
        }
    }

    // epilogue
    const float rl0 = 1.f / l0;
    const float rl1 = 1.f / l1;
    float* o0 = O + base + (size_t)(q0 + w16 + g) * DMODEL;
    float* o8 = O + base + (size_t)(q0 + w16 + g + 8) * DMODEL;
    #pragma unroll
    for (int n = 0; n < 8; n++) {
        const int col = n * 8 + tg * 2;
        *(float2*)(o0 + col) = make_float2(oacc[n][0] * rl0, oacc[n][1] * rl0);
        *(float2*)(o8 + col) = make_float2(oacc[n][2] * rl1, oacc[n][3] * rl1);
    }
}

// ---------------- launch ----------------------------------------------------
extern "C" void kernel_launch(void* const* d_in, const int* in_sizes, int n_in,
                              void* d_out, int out_size)
{
    const float* x   = (const float*)d_in[0];
    const float* wq  = (const float*)d_in[2];
    const float* bq  = (const float*)d_in[3];
    const float* wk  = (const float*)d_in[4];
    const float* bk  = (const float*)d_in[5];
    const float* wv  = (const float*)d_in[6];
    const float* bv  = (const float*)d_in[7];
    const float* wo  = (const float*)d_in[8];
    const float* bo  = (const float*)d_in[9];
    const float* w1  = (const float*)d_in[10];
    const float* b1  = (const float*)d_in[11];
    const float* w2  = (const float*)d_in[12];
    const float* b2  = (const float*)d_in[13];
    const float* l1a = (const float*)d_in[14];
    const float* l1b = (const float*)d_in[15];
    const float* l2a = (const float*)d_in[16];
    const float* l2b = (const float*)d_in[17];
    float* out = (float*)d_out;

    float *h, *q, *k, *v, *ctx, *x2, *ffn;
    cudaGetSymbolAddress((void**)&h,   g_h);
    cudaGetSymbolAddress((void**)&q,   g_q);
    cudaGetSymbolAddress((void**)&k,   g_k);
    cudaGetSymbolAddress((void**)&v,   g_v);
    cudaGetSymbolAddress((void**)&ctx, g_ctx);
    cudaGetSymbolAddress((void**)&x2,  g_x2);
    cudaGetSymbolAddress((void**)&ffn, g_ffn);

    cudaFuncSetAttribute(flash_mma, cudaFuncAttributeMaxDynamicSharedMemorySize,
                         FLASH_SMEM_BYTES);
    cudaFuncSetAttribute(mma_gemm_qkv, cudaFuncAttributeMaxDynamicSharedMemorySize,
                         GEMM_SMEM_BYTES);
    cudaFuncSetAttribute(mma_gemm<false, false>, cudaFuncAttributeMaxDynamicSharedMemorySize,
                         GEMM_SMEM_BYTES);
    cudaFuncSetAttribute(mma_gemm<false, true>, cudaFuncAttributeMaxDynamicSharedMemorySize,
                         GEMM_SMEM_BYTES);
    cudaFuncSetAttribute(mma_gemm<true, false>, cudaFuncAttributeMaxDynamicSharedMemorySize,
                         GEMM_SMEM_BYTES);

    const dim3 gProj(DMODEL / 256, NTOK / 128);          // (4, 64)
    const dim3 gQkv (DMODEL / 256, NTOK / 128, 3);       // (4, 64, 3)
    const dim3 gFfn1(DFF / 256,    NTOK / 128);          // (16, 64)

    ln_kernel<<<NTOK, 256>>>(x, h, l1a, l1b);
    mma_gemm_qkv<<<gQkv, 256, GEMM_SMEM_BYTES>>>(h, wq, wk, wv, bq, bk, bv, q, k, v);
    flash_mma<<<dim3(S_LEN / 128, HN, BATCH), 256, FLASH_SMEM_BYTES>>>(q, k, v, ctx);
    mma_gemm<false, true><<<gProj, 256, GEMM_SMEM_BYTES>>>(ctx, wo, bo, x, x2, DMODEL, DMODEL);
    ln_kernel<<<NTOK, 256>>>(x2, h, l2a, l2b);
    mma_gemm<true, false><<<gFfn1, 256, GEMM_SMEM_BYTES>>>(h, w1, b1, nullptr, ffn, DFF, DMODEL);
    mma_gemm<false, true><<<gProj, 256, GEMM_SMEM_BYTES>>>(ffn, w2, b2, x2, out, DMODEL, DFF);
}

// round 16
// speedup vs baseline: 1.3506x; 1.1360x over previous
#include <cuda_runtime.h>
#include <math.h>
#include <stdint.h>

#define S_LEN 2048
#define BATCH 4
#define DMODEL 1024
#define HN 16
#define DKH 64
#define DFF 4096
#define NTOK (BATCH * S_LEN)   // 8192

// ---------------- scratch (static device globals; no runtime allocation) ----
__device__ float g_h  [NTOK * DMODEL];
__device__ float g_q  [NTOK * DMODEL];
__device__ float g_k  [NTOK * DMODEL];
__device__ float g_v  [NTOK * DMODEL];
__device__ float g_ctx[NTOK * DMODEL];
__device__ float g_x2 [NTOK * DMODEL];
__device__ float g_ffn[(size_t)NTOK * DFF];

// ---------------- helpers ----------------------------------------------------
__device__ __forceinline__ unsigned f2tf32(float f) {
    unsigned u;
    asm("cvt.rna.tf32.f32 %0, %1;" : "=r"(u) : "f"(f));
    return u;
}
__device__ __forceinline__ float f2tf32f(float f) {
    return __uint_as_float(f2tf32(f));
}

#define MMA_TF32(d, a, b)                                                     \
    asm volatile(                                                             \
        "mma.sync.aligned.m16n8k8.row.col.f32.tf32.tf32.f32 "                 \
        "{%0,%1,%2,%3},{%4,%5,%6,%7},{%8,%9},{%0,%1,%2,%3};"                  \
        : "+f"((d)[0]), "+f"((d)[1]), "+f"((d)[2]), "+f"((d)[3])              \
        : "r"((a)[0]), "r"((a)[1]), "r"((a)[2]), "r"((a)[3]),                 \
          "r"((b)[0]), "r"((b)[1]))

// ---------------- LayerNorm (torch semantics) --------------------------------
__global__ void ln_kernel(const float* __restrict__ x, float* __restrict__ y,
                          const float* __restrict__ ga, const float* __restrict__ gb)
{
    int row = blockIdx.x;
    const float4* xr = (const float4*)(x + (size_t)row * DMODEL);
    float4* yr = (float4*)(y + (size_t)row * DMODEL);
    int t = threadIdx.x;
    float4 v = xr[t];
    float s  = v.x + v.y + v.z + v.w;
    float ss = v.x*v.x + v.y*v.y + v.z*v.z + v.w*v.w;
    #pragma unroll
    for (int o = 16; o > 0; o >>= 1) {
        s  += __shfl_xor_sync(0xffffffffu, s,  o);
        ss += __shfl_xor_sync(0xffffffffu, ss, o);
    }
    __shared__ float rs[8], rss[8];
    __shared__ float sh_mean, sh_inv, sh_beta;
    int w = t >> 5;
    if ((t & 31) == 0) { rs[w] = s; rss[w] = ss; }
    __syncthreads();
    if (t == 0) {
        float S = 0.f, SS = 0.f;
        #pragma unroll
        for (int i = 0; i < 8; i++) { S += rs[i]; SS += rss[i]; }
        float mean = S / (float)DMODEL;
        float var  = (SS - (float)DMODEL * mean * mean) / (float)(DMODEL - 1);
        var = fmaxf(var, 0.f);
        sh_mean = mean;
        sh_inv  = ga[0] / (sqrtf(var) + 1e-5f);
        sh_beta = gb[0];
    }
    __syncthreads();
    float mean = sh_mean, inv = sh_inv, beta = sh_beta;
    float4 o;
    o.x = (v.x - mean) * inv + beta;
    o.y = (v.y - mean) * inv + beta;
    o.z = (v.z - mean) * inv + beta;
    o.w = (v.w - mean) * inv + beta;
    yr[t] = o;
}

// ---------------- TF32 tensor-core GEMM (R3 config: best measured) -----------
// C[M,N] = A[M,K] @ W[N,K]^T + bias (+resid)(relu)
// Block 128x128, BK=32, 256 thr = 8 warps (2x4), warp tile 64x32, occ 1.
// LDG register prefetch -> cvt.rna at STS (conversion paid once per element)
// -> fragment LDS raw. Smem row stride 36: conflict-free fragment loads.
template<bool RELU, bool RESID>
__device__ __forceinline__ void gemm_body(
    const float* __restrict__ A, const float* __restrict__ W,
    const float* __restrict__ bias, const float* __restrict__ resid,
    float* __restrict__ C, int N, int K, int bm, int bn)
{
    __shared__ float As[128][36];
    __shared__ float Bs[128][36];

    const int tid  = threadIdx.x;
    const int lane = tid & 31;
    const int warp = tid >> 5;
    const int g    = lane >> 2;      // 0..7
    const int tg   = lane & 3;       // 0..3
    const int wm   = (warp >> 2) * 64;   // 0 or 64
    const int wn   = (warp & 3) * 32;    // 0,32,64,96

    // global load mapping: 4 float4 per thread per matrix per slab
    const int lrow = tid >> 3;       // 0..31 (+32*i)
    const int lc4  = tid & 7;        // float4 col within 32-float slab
    const float* Ag = A + (size_t)(bm + lrow) * K + lc4 * 4;
    const float* Wg = W + (size_t)(bn + lrow) * K + lc4 * 4;

    float acc[4][4][4];
    #pragma unroll
    for (int mi = 0; mi < 4; mi++)
        #pragma unroll
        for (int ni = 0; ni < 4; ni++)
            #pragma unroll
            for (int c = 0; c < 4; c++) acc[mi][ni][c] = 0.f;

    float4 pa[4], pb[4];
    #pragma unroll
    for (int i = 0; i < 4; i++) {
        pa[i] = *(const float4*)(Ag + (size_t)(32 * i) * K);
        pb[i] = *(const float4*)(Wg + (size_t)(32 * i) * K);
    }

    for (int k0 = 0; k0 < K; k0 += 32) {
        // commit prefetched slab to smem (tf32-rounded)
        #pragma unroll
        for (int i = 0; i < 4; i++) {
            float4 ta, tb;
            ta.x = f2tf32f(pa[i].x); ta.y = f2tf32f(pa[i].y);
            ta.z = f2tf32f(pa[i].z); ta.w = f2tf32f(pa[i].w);
            tb.x = f2tf32f(pb[i].x); tb.y = f2tf32f(pb[i].y);
            tb.z = f2tf32f(pb[i].z); tb.w = f2tf32f(pb[i].w);
            *(float4*)&As[lrow + 32 * i][lc4 * 4] = ta;
            *(float4*)&Bs[lrow + 32 * i][lc4 * 4] = tb;
        }
        __syncthreads();

        // prefetch next slab
        if (k0 + 32 < K) {
            #pragma unroll
            for (int i = 0; i < 4; i++) {
                pa[i] = *(const float4*)(Ag + k0 + 32 + (size_t)(32 * i) * K);
                pb[i] = *(const float4*)(Wg + k0 + 32 + (size_t)(32 * i) * K);
            }
        }

        // compute on current slab
        #pragma unroll
        for (int ks = 0; ks < 4; ks++) {
            unsigned a[4][4], b[4][2];
            const int c = ks * 8 + tg;
            #pragma unroll
            for (int mi = 0; mi < 4; mi++) {
                const int r = wm + mi * 16 + g;
                a[mi][0] = __float_as_uint(As[r][c]);
                a[mi][1] = __float_as_uint(As[r + 8][c]);
                a[mi][2] = __float_as_uint(As[r][c + 4]);
                a[mi][3] = __float_as_uint(As[r + 8][c + 4]);
            }
            #pragma unroll
            for (int ni = 0; ni < 4; ni++) {
                const int r = wn + ni * 8 + g;
                b[ni][0] = __float_as_uint(Bs[r][c]);
                b[ni][1] = __float_as_uint(Bs[r][c + 4]);
            }
            #pragma unroll
            for (int mi = 0; mi < 4; mi++)
                #pragma unroll
                for (int ni = 0; ni < 4; ni++)
                    MMA_TF32(acc[mi][ni], a[mi], b[ni]);
        }
        __syncthreads();
    }

    // epilogue
    #pragma unroll
    for (int mi = 0; mi < 4; mi++) {
        int row0 = bm + wm + mi * 16 + g;
        #pragma unroll
        for (int ni = 0; ni < 4; ni++) {
            int col = bn + wn + ni * 8 + tg * 2;
            float bia0 = bias[col], bia1 = bias[col + 1];
            float v0 = acc[mi][ni][0] + bia0;
            float v1 = acc[mi][ni][1] + bia1;
            float v2 = acc[mi][ni][2] + bia0;
            float v3 = acc[mi][ni][3] + bia1;
            if (RESID) {
                const float* r0 = resid + (size_t)row0 * N + col;
                const float* r8 = resid + (size_t)(row0 + 8) * N + col;
                v0 += r0[0]; v1 += r0[1];
                v2 += r8[0]; v3 += r8[1];
            }
            if (RELU) {
                v0 = fmaxf(v0, 0.f); v1 = fmaxf(v1, 0.f);
                v2 = fmaxf(v2, 0.f); v3 = fmaxf(v3, 0.f);
            }
            *(float2*)(C + (size_t)row0 * N + col)       = make_float2(v0, v1);
            *(float2*)(C + (size_t)(row0 + 8) * N + col) = make_float2(v2, v3);
        }
    }
}

template<bool RELU, bool RESID>
__global__ void __launch_bounds__(256, 1) mma_gemm(
    const float* __restrict__ A, const float* __restrict__ W,
    const float* __restrict__ bias, const float* __restrict__ resid,
    float* __restrict__ C, int N, int K)
{
    gemm_body<RELU, RESID>(A, W, bias, resid, C, N, K,
                           blockIdx.y * 128, blockIdx.x * 128);
}

// merged QKV: blockIdx.z selects weight/bias/output
__global__ void __launch_bounds__(256, 1) mma_gemm_qkv(
    const float* __restrict__ A,
    const float* __restrict__ wq, const float* __restrict__ wk, const float* __restrict__ wv,
    const float* __restrict__ bq, const float* __restrict__ bk, const float* __restrict__ bv,
    float* __restrict__ oq, float* __restrict__ ok, float* __restrict__ ov)
{
    const int z = blockIdx.z;
    const float* W = (z == 0) ? wq : (z == 1) ? wk : wv;
    const float* B = (z == 0) ? bq : (z == 1) ? bk : bv;
    float*       C = (z == 0) ? oq : (z == 1) ? ok : ov;
    gemm_body<false, false>(A, W, B, nullptr, C, DMODEL, DMODEL,
                            blockIdx.y * 128, blockIdx.x * 128);
}

// ---------------- Flash attention: Br=128, Bc=64, 8 warps (R15, unchanged) ---
#define FLASH_SMEM_BYTES ((128 * 68 + 64 * 68 + 128 * 68 + 64 * 72) * 4)  // 105472

__global__ void __launch_bounds__(256) flash_mma(
    const float* __restrict__ Q, const float* __restrict__ Kg,
    const float* __restrict__ Vg, float* __restrict__ O)
{
    extern __shared__ float fsm[];
    float* sq = fsm;                   // [128][68]
    float* sk = sq + 128 * 68;         // [64][68]
    float* sp = sk + 64 * 68;          // [128][68]
    float* sv = sp + 128 * 68;         // [64][72]

    const int qt = blockIdx.x, h = blockIdx.y, b = blockIdx.z;
    const int tid = threadIdx.x;
    const int lane = tid & 31;
    const int warp = tid >> 5;         // 0..7
    const int g = lane >> 2;
    const int tg = lane & 3;
    const int w16 = warp * 16;
    const int q0 = qt * 128;
    const size_t base = (size_t)b * S_LEN * DMODEL + (size_t)h * DKH;

    // load Q tile (tf32): 128 rows x 64 cols; 2 threads/row, 8 float4 each
    {
        const int r = tid >> 1;
        const int cb = (tid & 1) * 32;
        const float* src = Q + base + (size_t)(q0 + r) * DMODEL + cb;
        float* dst = sq + r * 68 + cb;
        #pragma unroll
        for (int i = 0; i < 8; i++) {
            float4 v = *(const float4*)(src + i * 4);
            v.x = f2tf32f(v.x); v.y = f2tf32f(v.y);
            v.z = f2tf32f(v.z); v.w = f2tf32f(v.w);
            *(float4*)(dst + i * 4) = v;
        }
    }

    float m0 = -1e30f, m1 = -1e30f, l0 = 0.f, l1 = 0.f;
    float oacc[8][4];
    #pragma unroll
    for (int n = 0; n < 8; n++)
        #pragma unroll
        for (int c = 0; c < 4; c++) oacc[n][c] = 0.f;

    for (int kt = 0; kt < S_LEN / 64; kt++) {
        const int j0 = kt * 64;
        __syncthreads();   // previous PV done before overwriting K/V
        // K/V: 64 rows x 64 cols; 4 threads/row, 4 float4 each
        {
            const int r = tid >> 2;
            const int cb = (tid & 3) * 16;
            const float* srck = Kg + base + (size_t)(j0 + r) * DMODEL + cb;
            const float* srcv = Vg + base + (size_t)(j0 + r) * DMODEL + cb;
            float* dk = sk + r * 68 + cb;
            float* dv = sv + r * 72 + cb;
            #pragma unroll
            for (int i = 0; i < 4; i++) {
                float4 kv = *(const float4*)(srck + i * 4);
                float4 vv = *(const float4*)(srcv + i * 4);
                kv.x = f2tf32f(kv.x); kv.y = f2tf32f(kv.y);
                kv.z = f2tf32f(kv.z); kv.w = f2tf32f(kv.w);
                vv.x = f2tf32f(vv.x); vv.y = f2tf32f(vv.y);
                vv.z = f2tf32f(vv.z); vv.w = f2tf32f(vv.w);
                *(float4*)(dk + i * 4) = kv;
                *(float4*)(dv + i * 4) = vv;
            }
        }
        __syncthreads();

        // ---- S = Q.K^T (warp: 16 rows x 64 kv) ----
        float sacc[8][4];
        #pragma unroll
        for (int n = 0; n < 8; n++)
            #pragma unroll
            for (int c = 0; c < 4; c++) sacc[n][c] = 0.f;

        #pragma unroll
        for (int k8 = 0; k8 < 8; k8++) {
            const int c = k8 * 8 + tg;
            unsigned a[4];
            a[0] = __float_as_uint(sq[(w16 + g) * 68 + c]);
            a[1] = __float_as_uint(sq[(w16 + g + 8) * 68 + c]);
            a[2] = __float_as_uint(sq[(w16 + g) * 68 + c + 4]);
            a[3] = __float_as_uint(sq[(w16 + g + 8) * 68 + c + 4]);
            #pragma unroll
            for (int n = 0; n < 8; n++) {
                unsigned bfr[2];
                bfr[0] = __float_as_uint(sk[(n * 8 + g) * 68 + c]);
                bfr[1] = __float_as_uint(sk[(n * 8 + g) * 68 + c + 4]);
                MMA_TF32(sacc[n], a, bfr);
            }
        }

        // ---- online softmax on fragments (rows g and g+8 of warp tile) ----
        float mx0 = -1e30f, mx1 = -1e30f;
        #pragma unroll
        for (int n = 0; n < 8; n++) {
            sacc[n][0] *= 0.125f; sacc[n][1] *= 0.125f;
            sacc[n][2] *= 0.125f; sacc[n][3] *= 0.125f;
            mx0 = fmaxf(mx0, fmaxf(sacc[n][0], sacc[n][1]));
            mx1 = fmaxf(mx1, fmaxf(sacc[n][2], sacc[n][3]));
        }
        mx0 = fmaxf(mx0, __shfl_xor_sync(0xffffffffu, mx0, 1));
        mx0 = fmaxf(mx0, __shfl_xor_sync(0xffffffffu, mx0, 2));
        mx1 = fmaxf(mx1, __shfl_xor_sync(0xffffffffu, mx1, 1));
        mx1 = fmaxf(mx1, __shfl_xor_sync(0xffffffffu, mx1, 2));

        const float mn0 = fmaxf(m0, mx0);
        const float mn1 = fmaxf(m1, mx1);
        const float corr0 = __expf(m0 - mn0);
        const float corr1 = __expf(m1 - mn1);
        float rs0 = 0.f, rs1 = 0.f;
        #pragma unroll
        for (int n = 0; n < 8; n++) {
            float p0 = __expf(sacc[n][0] - mn0);
            float p1 = __expf(sacc[n][1] - mn0);
            float p2 = __expf(sacc[n][2] - mn1);
            float p3 = __expf(sacc[n][3] - mn1);
            rs0 += p0 + p1;
            rs1 += p2 + p3;
            const int col = n * 8 + tg * 2;
            *(float2*)(sp + (w16 + g) * 68 + col) =
                make_float2(f2tf32f(p0), f2tf32f(p1));
            *(float2*)(sp + (w16 + g + 8) * 68 + col) =
                make_float2(f2tf32f(p2), f2tf32f(p3));
        }
        rs0 += __shfl_xor_sync(0xffffffffu, rs0, 1);
        rs0 += __shfl_xor_sync(0xffffffffu, rs0, 2);
        rs1 += __shfl_xor_sync(0xffffffffu, rs1, 1);
        rs1 += __shfl_xor_sync(0xffffffffu, rs1, 2);
        l0 = l0 * corr0 + rs0;
        l1 = l1 * corr1 + rs1;
        m0 = mn0; m1 = mn1;
        #pragma unroll
        for (int n = 0; n < 8; n++) {
            oacc[n][0] *= corr0; oacc[n][1] *= corr0;
            oacc[n][2] *= corr1; oacc[n][3] *= corr1;
        }
        __syncwarp();   // P rows are warp-private

        // ---- O += P.V ----
        #pragma unroll
        for (int k8 = 0; k8 < 8; k8++) {
            const int c = k8 * 8 + tg;
            unsigned a[4];
            a[0] = __float_as_uint(sp[(w16 + g) * 68 + c]);
            a[1] = __float_as_uint(sp[(w16 + g + 8) * 68 + c]);
            a[2] = __float_as_uint(sp[(w16 + g) * 68 + c + 4]);
            a[3] = __float_as_uint(sp[(w16 + g + 8) * 68 + c + 4]);
            #pragma unroll
            for (int n = 0; n < 8; n++) {
                unsigned bfr[2];
                bfr[0] = __float_as_uint(sv[c * 72 + n * 8 + g]);
                bfr[1] = __float_as_uint(sv[(c + 4) * 72 + n * 8 + g]);
                MMA_TF32(oacc[n], a, bfr);
            }
        }
    }

    // epilogue
    const float rl0 = 1.f / l0;
    const float rl1 = 1.f / l1;
    float* o0 = O + base + (size_t)(q0 + w16 + g) * DMODEL;
    float* o8 = O + base + (size_t)(q0 + w16 + g + 8) * DMODEL;
    #pragma unroll
    for (int n = 0; n < 8; n++) {
        const int col = n * 8 + tg * 2;
        *(float2*)(o0 + col) = make_float2(oacc[n][0] * rl0, oacc[n][1] * rl0);
        *(float2*)(o8 + col) = make_float2(oacc[n][2] * rl1, oacc[n][3] * rl1);
    }
}

// ---------------- launch ----------------------------------------------------
extern "C" void kernel_launch(void* const* d_in, const int* in_sizes, int n_in,
                              void* d_out, int out_size)
{
    const float* x   = (const float*)d_in[0];
    const float* wq  = (const float*)d_in[2];
    const float* bq  = (const float*)d_in[3];
    const float* wk  = (const float*)d_in[4];
    const float* bk  = (const float*)d_in[5];
    const float* wv  = (const float*)d_in[6];
    const float* bv  = (const float*)d_in[7];
    const float* wo  = (const float*)d_in[8];
    const float* bo  = (const float*)d_in[9];
    const float* w1  = (const float*)d_in[10];
    const float* b1  = (const float*)d_in[11];
    const float* w2  = (const float*)d_in[12];
    const float* b2  = (const float*)d_in[13];
    const float* l1a = (const float*)d_in[14];
    const float* l1b = (const float*)d_in[15];
    const float* l2a = (const float*)d_in[16];
    const float* l2b = (const float*)d_in[17];
    float* out = (float*)d_out;

    float *h, *q, *k, *v, *ctx, *x2, *ffn;
    cudaGetSymbolAddress((void**)&h,   g_h);
    cudaGetSymbolAddress((void**)&q,   g_q);
    cudaGetSymbolAddress((void**)&k,   g_k);
    cudaGetSymbolAddress((void**)&v,   g_v);
    cudaGetSymbolAddress((void**)&ctx, g_ctx);
    cudaGetSymbolAddress((void**)&x2,  g_x2);
    cudaGetSymbolAddress((void**)&ffn, g_ffn);

    cudaFuncSetAttribute(flash_mma, cudaFuncAttributeMaxDynamicSharedMemorySize,
                         FLASH_SMEM_BYTES);

    const dim3 gProj(DMODEL / 128, NTOK / 128);          // (8, 64)
    const dim3 gQkv (DMODEL / 128, NTOK / 128, 3);       // (8, 64, 3)
    const dim3 gFfn1(DFF / 128,    NTOK / 128);          // (32, 64)

    ln_kernel<<<NTOK, 256>>>(x, h, l1a, l1b);
    mma_gemm_qkv<<<gQkv, 256>>>(h, wq, wk, wv, bq, bk, bv, q, k, v);
    flash_mma<<<dim3(S_LEN / 128, HN, BATCH), 256, FLASH_SMEM_BYTES>>>(q, k, v, ctx);
    mma_gemm<false, true><<<gProj, 256>>>(ctx, wo, bo, x, x2, DMODEL, DMODEL);
    ln_kernel<<<NTOK, 256>>>(x2, h, l2a, l2b);
    mma_gemm<true, false><<<gFfn1, 256>>>(h, w1, b1, nullptr, ffn, DFF, DMODEL);
    mma_gemm<false, true><<<gProj, 256>>>(ffn, w2, b2, x2, out, DMODEL, DFF);
}